// round 12
// baseline (speedup 1.0000x reference)
#include <cuda_runtime.h>
#include <cuda_fp16.h>
#include <stdint.h>

#define N_NODES 50000
#define N_EDGES 600000
#define D 128
#define EPS 1e-5f
#define SCAN_BLOCKS 49   // ceil(50000/1024)

// ---------------- scratch (device globals; no allocations allowed) ----------
__device__ __half g_hn_h[N_NODES * D];   // layernormed features (fp16)
__device__ __half g_msg_h[N_NODES * D];  // aggregated message (fp16)
__device__ __half g_W_h[D * 2 * D];      // W fp16 (row-major [128][256])
__device__ int    g_counters[2 * N_NODES];  // [deg_in | deg_out]
__device__ float  g_inv_in[N_NODES];
__device__ float  g_inv_out[N_NODES];
__device__ int    g_rowstart[N_NODES];   // block-local exclusive scan of deg_in
__device__ int    g_blocksum[SCAN_BLOCKS];
__device__ int    g_blockoff[SCAN_BLOCKS];
__device__ int    g_epos[N_EDGES];       // per-edge rank within destination
__device__ int    g_csr_src[N_EDGES];
__device__ unsigned g_bar_cnt;           // zero-init; self-resetting
__device__ volatile unsigned g_bar_gen;  // barrier generation

#define DEG_IN  (g_counters)
#define DEG_OUT (g_counters + N_NODES)

__device__ __forceinline__ void cp_async16(void* smem, const void* gmem) {
    uint32_t s = (uint32_t)__cvta_generic_to_shared(smem);
    asm volatile("cp.async.cg.shared.global [%0], [%1], 16;" :: "r"(s), "l"(gmem));
}
#define CP_COMMIT() asm volatile("cp.async.commit_group;")
#define CP_WAIT(n)  asm volatile("cp.async.wait_group %0;" :: "n"(n))

// software grid barrier: all gridDim.x blocks are co-resident (1 block/SM)
__device__ __forceinline__ void gbar(unsigned target) {
    __threadfence();          // every thread's prior writes -> GPU scope
    __syncthreads();
    if (threadIdx.x == 0) {
        if (atomicAdd(&g_bar_cnt, 1u) == gridDim.x - 1) {
            g_bar_cnt = 0;
            __threadfence();
            g_bar_gen = target;
        } else {
            while (g_bar_gen < target) { __nanosleep(32); }
        }
    }
    __syncthreads();
}

__device__ __forceinline__ int row_begin_cg(int w) {
    return __ldcg(&g_rowstart[w]) + __ldcg(&g_blockoff[w >> 10]);
}

// ============ fused persistent kernel: zero -> LN+count+convw -> scan ->
// ============ scan-combine -> fill -> aggregate =============================
__global__ __launch_bounds__(1024, 1)
void k_fused(const float* __restrict__ h,
             const float* __restrict__ gamma,
             const float* __restrict__ beta,
             const float* __restrict__ W,
             const int* __restrict__ src,
             const int* __restrict__ dst) {
    __shared__ int warp_sums[32];
    __shared__ int sh2[64];

    const int tid  = threadIdx.x;
    const int nth  = gridDim.x * blockDim.x;
    const int gtid = blockIdx.x * blockDim.x + tid;
    const int lane = tid & 31;
    const int gwarp  = gtid >> 5;
    const int nwarps = nth >> 5;
    const unsigned base = g_bar_gen;

    // ---- P0: zero counters + convert W to fp16 ----
    for (int i = gtid; i < 2 * N_NODES; i += nth) g_counters[i] = 0;
    for (int i = gtid; i < (D * 2 * D) / 4; i += nth) {
        float4 v = *(const float4*)&W[i * 4];
        __half2 h0 = __float22half2_rn(make_float2(v.x, v.y));
        __half2 h1 = __float22half2_rn(make_float2(v.z, v.w));
        uint2 p;
        p.x = *(uint32_t*)&h0;
        p.y = *(uint32_t*)&h1;
        *(uint2*)&g_W_h[i * 4] = p;
    }
    gbar(base + 1);

    // ---- P1: degree count (+epos) and LayerNorm ----
    for (int i4 = gtid; i4 < N_EDGES / 4; i4 += nth) {
        int4 s = ((const int4*)src)[i4];
        int4 d = ((const int4*)dst)[i4];
        atomicAdd(&DEG_OUT[s.x], 1);
        atomicAdd(&DEG_OUT[s.y], 1);
        atomicAdd(&DEG_OUT[s.z], 1);
        atomicAdd(&DEG_OUT[s.w], 1);
        int4 p;
        p.x = atomicAdd(&DEG_IN[d.x], 1);
        p.y = atomicAdd(&DEG_IN[d.y], 1);
        p.z = atomicAdd(&DEG_IN[d.z], 1);
        p.w = atomicAdd(&DEG_IN[d.w], 1);
        ((int4*)g_epos)[i4] = p;
    }
    {
        float4 gm = ((const float4*)gamma)[lane];
        float4 bt = ((const float4*)beta)[lane];
        for (int row = gwarp; row < N_NODES; row += nwarps) {
            float4 v = ((const float4*)h)[row * 32 + lane];
            float s  = v.x + v.y + v.z + v.w;
            float sq = v.x * v.x + v.y * v.y + v.z * v.z + v.w * v.w;
            #pragma unroll
            for (int off = 16; off > 0; off >>= 1) {
                s  += __shfl_xor_sync(0xFFFFFFFF, s,  off);
                sq += __shfl_xor_sync(0xFFFFFFFF, sq, off);
            }
            float mu  = s * (1.0f / D);
            float var = sq * (1.0f / D) - mu * mu;
            float rs  = rsqrtf(var + EPS);
            float ox = (v.x - mu) * rs * gm.x + bt.x;
            float oy = (v.y - mu) * rs * gm.y + bt.y;
            float oz = (v.z - mu) * rs * gm.z + bt.z;
            float ow = (v.w - mu) * rs * gm.w + bt.w;
            __half2 h0 = __float22half2_rn(make_float2(ox, oy));
            __half2 h1 = __float22half2_rn(make_float2(oz, ow));
            uint2 pack;
            pack.x = *(uint32_t*)&h0;
            pack.y = *(uint32_t*)&h1;
            ((uint2*)g_hn_h)[row * 32 + lane] = pack;
        }
    }
    gbar(base + 2);

    // ---- P2: per-block scan of 1024 degrees (blocks 0..48) + inv-sqrt ----
    if (blockIdx.x < SCAN_BLOCKS) {
        int i = blockIdx.x * 1024 + tid;
        int wid = tid >> 5;
        int v = 0;
        if (i < N_NODES) {
            v = __ldcg(&DEG_IN[i]);           // atomics landed in L2
            int dout = __ldcg(&DEG_OUT[i]);
            g_inv_in[i]  = rsqrtf((float)(v    < 1 ? 1 : v));
            g_inv_out[i] = rsqrtf((float)(dout < 1 ? 1 : dout));
        }
        int incl = v;
        #pragma unroll
        for (int off = 1; off < 32; off <<= 1) {
            int n = __shfl_up_sync(0xFFFFFFFF, incl, off);
            if (lane >= off) incl += n;
        }
        if (lane == 31) warp_sums[wid] = incl;
        __syncthreads();
        if (wid == 0) {
            int ws = warp_sums[lane];
            int wi = ws;
            #pragma unroll
            for (int off = 1; off < 32; off <<= 1) {
                int n = __shfl_up_sync(0xFFFFFFFF, wi, off);
                if (lane >= off) wi += n;
            }
            warp_sums[lane] = wi - ws;
            if (lane == 31) g_blocksum[blockIdx.x] = wi;
        }
        __syncthreads();
        if (i < N_NODES)
            g_rowstart[i] = incl - v + warp_sums[wid];
    }
    gbar(base + 3);

    // ---- P2b: block 0 scans the 49 block sums ----
    if (blockIdx.x == 0) {
        int bv = (tid < SCAN_BLOCKS) ? __ldcg(&g_blocksum[tid]) : 0;
        if (tid < 64) sh2[tid] = bv;
        __syncthreads();
        #pragma unroll
        for (int off = 1; off < 64; off <<= 1) {
            int x = (tid >= off && tid < 64) ? sh2[tid - off] : 0;
            __syncthreads();
            if (tid < 64) sh2[tid] += x;
            __syncthreads();
        }
        if (tid < SCAN_BLOCKS)
            g_blockoff[tid] = sh2[tid] - bv;   // exclusive
    }
    gbar(base + 4);

    // ---- P3: scatter edges into CSR (no atomics) ----
    for (int i4 = gtid; i4 < N_EDGES / 4; i4 += nth) {
        int4 s = ((const int4*)src)[i4];
        int4 d = ((const int4*)dst)[i4];
        int4 p = ((const int4*)g_epos)[i4];
        g_csr_src[row_begin_cg(d.x) + p.x] = s.x;
        g_csr_src[row_begin_cg(d.y) + p.y] = s.y;
        g_csr_src[row_begin_cg(d.z) + p.z] = s.z;
        g_csr_src[row_begin_cg(d.w) + p.w] = s.w;
    }
    gbar(base + 5);

    // ---- P4: aggregation (warp per destination node, unroll 4) ----
    for (int node = gwarp; node < N_NODES; node += nwarps) {
        int e0 = row_begin_cg(node);
        int e1 = (node + 1 < N_NODES) ? row_begin_cg(node + 1) : N_EDGES;

        float ax0 = 0.f, ay0 = 0.f, az0 = 0.f, aw0 = 0.f;
        float ax1 = 0.f, ay1 = 0.f, az1 = 0.f, aw1 = 0.f;
        int e = e0;
        for (; e + 4 <= e1; e += 4) {
            int s0 = __ldcg(&g_csr_src[e]);
            int s1 = __ldcg(&g_csr_src[e + 1]);
            int s2 = __ldcg(&g_csr_src[e + 2]);
            int s3 = __ldcg(&g_csr_src[e + 3]);
            float w0 = g_inv_out[s0];
            float w1 = g_inv_out[s1];
            float w2 = g_inv_out[s2];
            float w3 = g_inv_out[s3];
            uint2 u0 = ((const uint2*)g_hn_h)[s0 * 32 + lane];
            uint2 u1 = ((const uint2*)g_hn_h)[s1 * 32 + lane];
            uint2 u2 = ((const uint2*)g_hn_h)[s2 * 32 + lane];
            uint2 u3 = ((const uint2*)g_hn_h)[s3 * 32 + lane];
            float2 f00 = __half22float2(*(__half2*)&u0.x);
            float2 f01 = __half22float2(*(__half2*)&u0.y);
            float2 f10 = __half22float2(*(__half2*)&u1.x);
            float2 f11 = __half22float2(*(__half2*)&u1.y);
            float2 f20 = __half22float2(*(__half2*)&u2.x);
            float2 f21 = __half22float2(*(__half2*)&u2.y);
            float2 f30 = __half22float2(*(__half2*)&u3.x);
            float2 f31 = __half22float2(*(__half2*)&u3.y);
            ax0 += f00.x * w0;  ay0 += f00.y * w0;
            az0 += f01.x * w0;  aw0 += f01.y * w0;
            ax1 += f10.x * w1;  ay1 += f10.y * w1;
            az1 += f11.x * w1;  aw1 += f11.y * w1;
            ax0 += f20.x * w2;  ay0 += f20.y * w2;
            az0 += f21.x * w2;  aw0 += f21.y * w2;
            ax1 += f30.x * w3;  ay1 += f30.y * w3;
            az1 += f31.x * w3;  aw1 += f31.y * w3;
        }
        for (; e < e1; e++) {
            int s = __ldcg(&g_csr_src[e]);
            float w = g_inv_out[s];
            uint2 u = ((const uint2*)g_hn_h)[s * 32 + lane];
            float2 f0 = __half22float2(*(__half2*)&u.x);
            float2 f1 = __half22float2(*(__half2*)&u.y);
            ax0 += f0.x * w;  ay0 += f0.y * w;
            az0 += f1.x * w;  aw0 += f1.y * w;
        }
        float wi = g_inv_in[node];
        __half2 h0 = __float22half2_rn(make_float2((ax0 + ax1) * wi, (ay0 + ay1) * wi));
        __half2 h1 = __float22half2_rn(make_float2((az0 + az1) * wi, (aw0 + aw1) * wi));
        uint2 pack;
        pack.x = *(uint32_t*)&h0;
        pack.y = *(uint32_t*)&h1;
        ((uint2*)g_msg_h)[node * 32 + lane] = pack;
    }
}

// ---------------- K6: FP16 MMA GEMM, cp.async pipelined (round-9 proven) -----
#define GBM 128
#define APAD 72    // A row stride in halfs
#define WPAD 264   // W row stride in halfs
#define SMEM_GEMM ((2 * GBM * APAD + 128 * WPAD) * 2)   // 104448 bytes

__global__ __launch_bounds__(256, 2)
void k_gemm(const float* __restrict__ bias, // [128]
            float* __restrict__ out) {      // [N][128] fp32
    extern __shared__ __half sm[];
    __half* As = sm;                        // [2][128][APAD]
    __half* Ws = sm + 2 * GBM * APAD;       // [128][WPAD]

    int tid  = threadIdx.x;
    int warp = tid >> 5;
    int lane = tid & 31;
    int rowBase = blockIdx.x * GBM;

    auto issue_a = [&](int i) {
        const __half* Asrc = (i < 2) ? g_hn_h : g_msg_h;
        int kOff = (i * 64) & (D - 1);
        int buf = i & 1;
        #pragma unroll
        for (int it = 0; it < 4; it++) {
            int id = tid + it * 256;
            int r  = id >> 3;
            int c8 = id & 7;
            int gr = rowBase + r;
            if (gr > N_NODES - 1) gr = N_NODES - 1;   // clamp; result discarded
            cp_async16(&As[(buf * GBM + r) * APAD + c8 * 8],
                       &Asrc[gr * D + kOff + c8 * 8]);
        }
    };

    #pragma unroll
    for (int it = 0; it < 16; it++) {
        int id = tid + it * 256;
        int n  = id >> 5;
        int c8 = id & 31;
        cp_async16(&Ws[n * WPAD + c8 * 8], &g_W_h[n * 256 + c8 * 8]);
    }
    issue_a(0);
    CP_COMMIT();

    float acc[16][4];
    #pragma unroll
    for (int j = 0; j < 16; j++)
        #pragma unroll
        for (int c = 0; c < 4; c++) acc[j][c] = 0.f;

    int q = lane & 3;
    int g = lane >> 2;
    int r0 = warp * 16;

    #pragma unroll
    for (int i = 0; i < 4; i++) {
        if (i < 3) {
            issue_a(i + 1);
            CP_COMMIT();
            CP_WAIT(1);
        } else {
            CP_WAIT(0);
        }
        __syncthreads();

        const __half* Ab = &As[(i & 1) * GBM * APAD];
        int kw = i * 64;
        #pragma unroll
        for (int k0 = 0; k0 < 64; k0 += 16) {
            uint32_t a0 = *(const uint32_t*)&Ab[(r0 + g) * APAD + k0 + 2 * q];
            uint32_t a1 = *(const uint32_t*)&Ab[(r0 + g + 8) * APAD + k0 + 2 * q];
            uint32_t a2 = *(const uint32_t*)&Ab[(r0 + g) * APAD + k0 + 2 * q + 8];
            uint32_t a3 = *(const uint32_t*)&Ab[(r0 + g + 8) * APAD + k0 + 2 * q + 8];
            #pragma unroll
            for (int j = 0; j < 16; j++) {
                uint32_t b0 = *(const uint32_t*)&Ws[(j * 8 + g) * WPAD + kw + k0 + 2 * q];
                uint32_t b1 = *(const uint32_t*)&Ws[(j * 8 + g) * WPAD + kw + k0 + 2 * q + 8];
                asm volatile(
                    "mma.sync.aligned.m16n8k16.row.col.f32.f16.f16.f32 "
                    "{%0,%1,%2,%3}, {%4,%5,%6,%7}, {%8,%9}, {%0,%1,%2,%3};"
                    : "+f"(acc[j][0]), "+f"(acc[j][1]),
                      "+f"(acc[j][2]), "+f"(acc[j][3])
                    : "r"(a0), "r"(a1), "r"(a2), "r"(a3), "r"(b0), "r"(b1));
            }
        }
        __syncthreads();
    }

    int row0 = rowBase + warp * 16 + g;
    int row1 = row0 + 8;
    #pragma unroll
    for (int j = 0; j < 16; j++) {
        int col = j * 8 + q * 2;
        float b0 = __ldg(&bias[col]);
        float b1 = __ldg(&bias[col + 1]);
        if (row0 < N_NODES) {
            float2 o = make_float2(acc[j][0] + b0, acc[j][1] + b1);
            *(float2*)&out[row0 * D + col] = o;
        }
        if (row1 < N_NODES) {
            float2 o = make_float2(acc[j][2] + b0, acc[j][3] + b1);
            *(float2*)&out[row1 * D + col] = o;
        }
    }
}

// ---------------- launcher ---------------------------------------------------
extern "C" void kernel_launch(void* const* d_in, const int* in_sizes, int n_in,
                              void* d_out, int out_size) {
    const float* h     = (const float*)d_in[0];
    const int*   ei    = (const int*)d_in[1];   // [2][E] int32
    const float* gamma = (const float*)d_in[2];
    const float* beta  = (const float*)d_in[3];
    const float* W     = (const float*)d_in[4];
    const float* bias  = (const float*)d_in[5];
    float*       out   = (float*)d_out;

    const int* src = ei;
    const int* dst = ei + N_EDGES;

    int dev = 0, sms = 0;
    cudaGetDevice(&dev);
    cudaDeviceGetAttribute(&sms, cudaDevAttrMultiProcessorCount, dev);
    if (sms < SCAN_BLOCKS) sms = SCAN_BLOCKS;   // scan needs >= 49 blocks

    cudaFuncSetAttribute(k_gemm, cudaFuncAttributeMaxDynamicSharedMemorySize,
                         SMEM_GEMM);

    // one persistent kernel (1 block per SM, all co-resident) + GEMM
    k_fused<<<sms, 1024>>>(h, gamma, beta, W, src, dst);
    k_gemm<<<(N_NODES + GBM - 1) / GBM, 256, SMEM_GEMM>>>(bias, out);
}

// round 14
// speedup vs baseline: 1.2979x; 1.2979x over previous
#include <cuda_runtime.h>
#include <cuda_fp16.h>
#include <stdint.h>

#define N_NODES 50000
#define N_EDGES 600000
#define D 128
#define EPS 1e-5f
#define SCAN_BLOCKS 49   // ceil(50000/1024)

// ---------------- scratch (device globals; no allocations allowed) ----------
__device__ __half g_hn_h[N_NODES * D];   // layernormed features (fp16)
__device__ __half g_msg_h[N_NODES * D];  // aggregated message (fp16)
__device__ __half g_W_h[D * 2 * D];      // W fp16 (row-major [128][256])
__device__ int    g_counters[2 * N_NODES];  // [deg_in | deg_out]
__device__ float  g_inv_in[N_NODES];
__device__ float  g_inv_out[N_NODES];
__device__ int    g_rowstart[N_NODES];   // block-local exclusive scan of deg_in
__device__ int    g_blocksum[SCAN_BLOCKS];
__device__ int    g_blockoff[SCAN_BLOCKS];
__device__ int    g_epos[N_EDGES];       // per-edge rank within destination
__device__ int    g_csr_src[N_EDGES];

#define DEG_IN  (g_counters)
#define DEG_OUT (g_counters + N_NODES)

__device__ __forceinline__ int row_begin(int w) {
    return g_rowstart[w] + g_blockoff[w >> 10];
}

__device__ __forceinline__ void cp_async16(void* smem, const void* gmem) {
    uint32_t s = (uint32_t)__cvta_generic_to_shared(smem);
    asm volatile("cp.async.cg.shared.global [%0], [%1], 16;" :: "r"(s), "l"(gmem));
}
#define CP_COMMIT() asm volatile("cp.async.commit_group;")
#define CP_WAIT(n)  asm volatile("cp.async.wait_group %0;" :: "n"(n))

// ---------------- K1: degree counts + per-edge rank (4 edges/thread) ---------
__global__ void k_count(const int* __restrict__ src,
                        const int* __restrict__ dst) {
    int i4 = blockIdx.x * blockDim.x + threadIdx.x;
    if (i4 < N_EDGES / 4) {
        int4 s = ((const int4*)src)[i4];
        int4 d = ((const int4*)dst)[i4];
        atomicAdd(&DEG_OUT[s.x], 1);
        atomicAdd(&DEG_OUT[s.y], 1);
        atomicAdd(&DEG_OUT[s.z], 1);
        atomicAdd(&DEG_OUT[s.w], 1);
        int4 p;
        p.x = atomicAdd(&DEG_IN[d.x], 1);
        p.y = atomicAdd(&DEG_IN[d.y], 1);
        p.z = atomicAdd(&DEG_IN[d.z], 1);
        p.w = atomicAdd(&DEG_IN[d.w], 1);
        ((int4*)g_epos)[i4] = p;
    }
}

// ---------------- K1b: convert W to fp16 -------------------------------------
__global__ void k_convw(const float* __restrict__ W) {
    int i = blockIdx.x * blockDim.x + threadIdx.x;   // over float4 groups
    if (i < (D * 2 * D) / 4) {
        float4 v = *(const float4*)&W[i * 4];
        __half2 h0 = __float22half2_rn(make_float2(v.x, v.y));
        __half2 h1 = __float22half2_rn(make_float2(v.z, v.w));
        uint2 p;
        p.x = *(uint32_t*)&h0;
        p.y = *(uint32_t*)&h1;
        *(uint2*)&g_W_h[i * 4] = p;
    }
}

// ---------------- K2: LayerNorm (warp per row) -> fp16 (pure) ----------------
__global__ void k_layernorm(const float* __restrict__ h,
                            const float* __restrict__ gamma,
                            const float* __restrict__ beta) {
    int warp = (blockIdx.x * blockDim.x + threadIdx.x) >> 5;
    int lane = threadIdx.x & 31;
    if (warp >= N_NODES) return;

    float4 v = ((const float4*)h)[warp * 32 + lane];
    float s  = v.x + v.y + v.z + v.w;
    float sq = v.x * v.x + v.y * v.y + v.z * v.z + v.w * v.w;
    #pragma unroll
    for (int off = 16; off > 0; off >>= 1) {
        s  += __shfl_xor_sync(0xFFFFFFFF, s,  off);
        sq += __shfl_xor_sync(0xFFFFFFFF, sq, off);
    }
    float mu  = s * (1.0f / D);
    float var = sq * (1.0f / D) - mu * mu;
    float rs  = rsqrtf(var + EPS);

    float4 g = ((const float4*)gamma)[lane];
    float4 b = ((const float4*)beta)[lane];
    float ox = (v.x - mu) * rs * g.x + b.x;
    float oy = (v.y - mu) * rs * g.y + b.y;
    float oz = (v.z - mu) * rs * g.z + b.z;
    float ow = (v.w - mu) * rs * g.w + b.w;

    __half2 h0 = __float22half2_rn(make_float2(ox, oy));
    __half2 h1 = __float22half2_rn(make_float2(oz, ow));
    uint2 pack;
    pack.x = *(uint32_t*)&h0;
    pack.y = *(uint32_t*)&h1;
    ((uint2*)g_hn_h)[warp * 32 + lane] = pack;
}

// ---------------- K3a: per-block scan of deg_in + inv-sqrt degrees ----------
__global__ __launch_bounds__(1024)
void k_scan_local() {
    __shared__ int warp_sums[32];
    int t = threadIdx.x;
    int i = blockIdx.x * 1024 + t;
    int lane = t & 31;
    int wid = t >> 5;

    int v = 0;
    if (i < N_NODES) {
        v = DEG_IN[i];
        int dout = DEG_OUT[i];
        g_inv_in[i]  = rsqrtf((float)(v    < 1 ? 1 : v));
        g_inv_out[i] = rsqrtf((float)(dout < 1 ? 1 : dout));
    }
    int incl = v;
    #pragma unroll
    for (int off = 1; off < 32; off <<= 1) {
        int n = __shfl_up_sync(0xFFFFFFFF, incl, off);
        if (lane >= off) incl += n;
    }
    if (lane == 31) warp_sums[wid] = incl;
    __syncthreads();
    if (wid == 0) {
        int ws = warp_sums[lane];
        int wi = ws;
        #pragma unroll
        for (int off = 1; off < 32; off <<= 1) {
            int n = __shfl_up_sync(0xFFFFFFFF, wi, off);
            if (lane >= off) wi += n;
        }
        warp_sums[lane] = wi - ws;   // exclusive warp offset
        if (lane == 31) g_blocksum[blockIdx.x] = wi;
    }
    __syncthreads();
    if (i < N_NODES)
        g_rowstart[i] = incl - v + warp_sums[wid];
}

// ---------------- K3b: scan the 49 block sums -> blockoff -------------------
__global__ void k_scan_block() {
    __shared__ int sh[64];
    int t = threadIdx.x;
    int v = (t < SCAN_BLOCKS) ? g_blocksum[t] : 0;
    sh[t] = v;
    __syncthreads();
    #pragma unroll
    for (int off = 1; off < 64; off <<= 1) {
        int x = (t >= off) ? sh[t - off] : 0;
        __syncthreads();
        sh[t] += x;
        __syncthreads();
    }
    if (t < SCAN_BLOCKS)
        g_blockoff[t] = sh[t] - v;   // exclusive
}

// ---------------- K4: scatter edges into CSR (no atomics, 4/thread) ----------
__global__ void k_fill_csr(const int* __restrict__ src,
                           const int* __restrict__ dst) {
    int i4 = blockIdx.x * blockDim.x + threadIdx.x;
    if (i4 < N_EDGES / 4) {
        int4 s = ((const int4*)src)[i4];
        int4 d = ((const int4*)dst)[i4];
        int4 p = ((const int4*)g_epos)[i4];
        g_csr_src[row_begin(d.x) + p.x] = s.x;
        g_csr_src[row_begin(d.y) + p.y] = s.y;
        g_csr_src[row_begin(d.z) + p.z] = s.z;
        g_csr_src[row_begin(d.w) + p.w] = s.w;
    }
}

// ---------------- K5: aggregation (warp per dst node, fp16, unroll 4) --------
__global__ void k_aggregate() {
    int warp = (blockIdx.x * blockDim.x + threadIdx.x) >> 5;
    int lane = threadIdx.x & 31;
    if (warp >= N_NODES) return;

    int e0 = row_begin(warp);
    int e1 = (warp + 1 < N_NODES) ? row_begin(warp + 1) : N_EDGES;

    float ax0 = 0.f, ay0 = 0.f, az0 = 0.f, aw0 = 0.f;
    float ax1 = 0.f, ay1 = 0.f, az1 = 0.f, aw1 = 0.f;
    int e = e0;
    for (; e + 4 <= e1; e += 4) {
        int s0 = __ldg(&g_csr_src[e]);
        int s1 = __ldg(&g_csr_src[e + 1]);
        int s2 = __ldg(&g_csr_src[e + 2]);
        int s3 = __ldg(&g_csr_src[e + 3]);
        float w0 = g_inv_out[s0];
        float w1 = g_inv_out[s1];
        float w2 = g_inv_out[s2];
        float w3 = g_inv_out[s3];
        uint2 u0 = ((const uint2*)g_hn_h)[s0 * 32 + lane];
        uint2 u1 = ((const uint2*)g_hn_h)[s1 * 32 + lane];
        uint2 u2 = ((const uint2*)g_hn_h)[s2 * 32 + lane];
        uint2 u3 = ((const uint2*)g_hn_h)[s3 * 32 + lane];
        float2 f00 = __half22float2(*(__half2*)&u0.x);
        float2 f01 = __half22float2(*(__half2*)&u0.y);
        float2 f10 = __half22float2(*(__half2*)&u1.x);
        float2 f11 = __half22float2(*(__half2*)&u1.y);
        float2 f20 = __half22float2(*(__half2*)&u2.x);
        float2 f21 = __half22float2(*(__half2*)&u2.y);
        float2 f30 = __half22float2(*(__half2*)&u3.x);
        float2 f31 = __half22float2(*(__half2*)&u3.y);
        ax0 += f00.x * w0;  ay0 += f00.y * w0;
        az0 += f01.x * w0;  aw0 += f01.y * w0;
        ax1 += f10.x * w1;  ay1 += f10.y * w1;
        az1 += f11.x * w1;  aw1 += f11.y * w1;
        ax0 += f20.x * w2;  ay0 += f20.y * w2;
        az0 += f21.x * w2;  aw0 += f21.y * w2;
        ax1 += f30.x * w3;  ay1 += f30.y * w3;
        az1 += f31.x * w3;  aw1 += f31.y * w3;
    }
    for (; e < e1; e++) {
        int s = __ldg(&g_csr_src[e]);
        float w = g_inv_out[s];
        uint2 u = ((const uint2*)g_hn_h)[s * 32 + lane];
        float2 f0 = __half22float2(*(__half2*)&u.x);
        float2 f1 = __half22float2(*(__half2*)&u.y);
        ax0 += f0.x * w;  ay0 += f0.y * w;
        az0 += f1.x * w;  aw0 += f1.y * w;
    }
    float wi = g_inv_in[warp];
    __half2 h0 = __float22half2_rn(make_float2((ax0 + ax1) * wi, (ay0 + ay1) * wi));
    __half2 h1 = __float22half2_rn(make_float2((az0 + az1) * wi, (aw0 + aw1) * wi));
    uint2 pack;
    pack.x = *(uint32_t*)&h0;
    pack.y = *(uint32_t*)&h1;
    ((uint2*)g_msg_h)[warp * 32 + lane] = pack;
}

// ---------------- K6: FP16 MMA GEMM, 512 threads (16 warps: 8 M x 2 N) -------
#define GBM 128
#define APAD 72    // A row stride in halfs
#define WPAD 264   // W row stride in halfs
#define SMEM_GEMM ((2 * GBM * APAD + 128 * WPAD) * 2)   // 104448 bytes

__global__ __launch_bounds__(512, 2)
void k_gemm(const float* __restrict__ bias, // [128]
            float* __restrict__ out) {      // [N][128] fp32
    extern __shared__ __half sm[];
    __half* As = sm;                        // [2][128][APAD]
    __half* Ws = sm + 2 * GBM * APAD;       // [128][WPAD]

    int tid  = threadIdx.x;
    int warp = tid >> 5;
    int lane = tid & 31;
    int mg   = warp & 7;        // m-group: rows [mg*16, mg*16+16)
    int ng   = warp >> 3;       // n-group: cols [ng*64, ng*64+64)
    int rowBase = blockIdx.x * GBM;

    auto issue_a = [&](int i) {
        const __half* Asrc = (i < 2) ? g_hn_h : g_msg_h;
        int kOff = (i * 64) & (D - 1);
        int buf = i & 1;
        #pragma unroll
        for (int it = 0; it < 2; it++) {
            int id = tid + it * 512;    // 0..1023 uint4 slots
            int r  = id >> 3;
            int c8 = id & 7;
            int gr = rowBase + r;
            if (gr > N_NODES - 1) gr = N_NODES - 1;   // clamp; result discarded
            cp_async16(&As[(buf * GBM + r) * APAD + c8 * 8],
                       &Asrc[gr * D + kOff + c8 * 8]);
        }
    };

    // prologue: whole W = 128 rows x 256 halfs = 4096 uint4 slots
    #pragma unroll
    for (int it = 0; it < 8; it++) {
        int id = tid + it * 512;    // 0..4095
        int n  = id >> 5;           // 0..127
        int c8 = id & 31;           // 0..31 -> covers all 256 halfs per row
        cp_async16(&Ws[n * WPAD + c8 * 8], &g_W_h[n * 256 + c8 * 8]);
    }
    issue_a(0);
    CP_COMMIT();

    float acc[8][4];
    #pragma unroll
    for (int j = 0; j < 8; j++)
        #pragma unroll
        for (int c = 0; c < 4; c++) acc[j][c] = 0.f;

    int q = lane & 3;
    int g = lane >> 2;
    int r0 = mg * 16;

    #pragma unroll
    for (int i = 0; i < 4; i++) {
        if (i < 3) {
            issue_a(i + 1);
            CP_COMMIT();
            CP_WAIT(1);
        } else {
            CP_WAIT(0);
        }
        __syncthreads();

        const __half* Ab = &As[(i & 1) * GBM * APAD];
        int kw = i * 64;
        #pragma unroll
        for (int k0 = 0; k0 < 64; k0 += 16) {
            uint32_t a0 = *(const uint32_t*)&Ab[(r0 + g) * APAD + k0 + 2 * q];
            uint32_t a1 = *(const uint32_t*)&Ab[(r0 + g + 8) * APAD + k0 + 2 * q];
            uint32_t a2 = *(const uint32_t*)&Ab[(r0 + g) * APAD + k0 + 2 * q + 8];
            uint32_t a3 = *(const uint32_t*)&Ab[(r0 + g + 8) * APAD + k0 + 2 * q + 8];
            #pragma unroll
            for (int j = 0; j < 8; j++) {
                int n = ng * 64 + j * 8 + g;
                uint32_t b0 = *(const uint32_t*)&Ws[n * WPAD + kw + k0 + 2 * q];
                uint32_t b1 = *(const uint32_t*)&Ws[n * WPAD + kw + k0 + 2 * q + 8];
                asm volatile(
                    "mma.sync.aligned.m16n8k16.row.col.f32.f16.f16.f32 "
                    "{%0,%1,%2,%3}, {%4,%5,%6,%7}, {%8,%9}, {%0,%1,%2,%3};"
                    : "+f"(acc[j][0]), "+f"(acc[j][1]),
                      "+f"(acc[j][2]), "+f"(acc[j][3])
                    : "r"(a0), "r"(a1), "r"(a2), "r"(a3), "r"(b0), "r"(b1));
            }
        }
        __syncthreads();
    }

    // epilogue: bias + store
    int row0 = rowBase + mg * 16 + g;
    int row1 = row0 + 8;
    #pragma unroll
    for (int j = 0; j < 8; j++) {
        int col = ng * 64 + j * 8 + q * 2;
        float b0 = __ldg(&bias[col]);
        float b1 = __ldg(&bias[col + 1]);
        if (row0 < N_NODES) {
            float2 o = make_float2(acc[j][0] + b0, acc[j][1] + b1);
            *(float2*)&out[row0 * D + col] = o;
        }
        if (row1 < N_NODES) {
            float2 o = make_float2(acc[j][2] + b0, acc[j][3] + b1);
            *(float2*)&out[row1 * D + col] = o;
        }
    }
}

// ---------------- launcher (fork-join streams inside the capture) -----------
extern "C" void kernel_launch(void* const* d_in, const int* in_sizes, int n_in,
                              void* d_out, int out_size) {
    const float* h     = (const float*)d_in[0];
    const int*   ei    = (const int*)d_in[1];   // [2][E] int32
    const float* gamma = (const float*)d_in[2];
    const float* beta  = (const float*)d_in[3];
    const float* W     = (const float*)d_in[4];
    const float* bias  = (const float*)d_in[5];
    float*       out   = (float*)d_out;

    const int* src = ei;
    const int* dst = ei + N_EDGES;

    cudaFuncSetAttribute(k_gemm, cudaFuncAttributeMaxDynamicSharedMemorySize,
                         SMEM_GEMM);

    cudaStream_t s2;
    cudaStreamCreateWithFlags(&s2, cudaStreamNonBlocking);
    cudaEvent_t evFork, evJoin;
    cudaEventCreateWithFlags(&evFork, cudaEventDisableTiming);
    cudaEventCreateWithFlags(&evJoin, cudaEventDisableTiming);

    void* counters_ptr = nullptr;
    cudaGetSymbolAddress(&counters_ptr, g_counters);
    cudaMemsetAsync(counters_ptr, 0, 2 * N_NODES * sizeof(int), 0);

    // fork: s2 runs LN + W conversion concurrent with the edge chain
    cudaEventRecord(evFork, 0);
    cudaStreamWaitEvent(s2, evFork, 0);
    k_layernorm<<<(N_NODES * 32 + 255) / 256, 256, 0, s2>>>(h, gamma, beta);
    k_convw<<<((D * 2 * D / 4) + 255) / 256, 256, 0, s2>>>(W);
    cudaEventRecord(evJoin, s2);

    // main stream: edge chain
    k_count<<<(N_EDGES / 4 + 255) / 256, 256>>>(src, dst);
    k_scan_local<<<SCAN_BLOCKS, 1024>>>();
    k_scan_block<<<1, 64>>>();
    k_fill_csr<<<(N_EDGES / 4 + 255) / 256, 256>>>(src, dst);

    // join, then aggregate + GEMM
    cudaStreamWaitEvent(0, evJoin, 0);
    k_aggregate<<<(N_NODES * 32 + 255) / 256, 256>>>();
    k_gemm<<<(N_NODES + GBM - 1) / GBM, 512, SMEM_GEMM>>>(bias, out);
}